// round 1
// baseline (speedup 1.0000x reference)
#include <cuda_runtime.h>
#include <math.h>

// Problem constants
#define NTOK 16384      // B*S = 32*512
#define HDIM 2048
#define FPN  1024
#define SPN  1024
#define NCOLS 2049      // 1 + FP + SP
#define C_LD  2064      // padded leading dim for C scratch
#define OUT_COLS 2050   // 2 + FP + SP

// Device scratch (allocation-free rule: __device__ globals)
__device__ float g_W[(size_t)NCOLS * HDIM];      // packed [NCOLS][H], row-major
__device__ float g_bias[NCOLS];
__device__ float g_C[(size_t)NTOK * C_LD];       // logits scratch

// ---------------------------------------------------------------------------
// Pack W_end / W_hcw / W_roo into one contiguous [2049, 2048] matrix + bias.
// ---------------------------------------------------------------------------
__global__ void pack_kernel(const float* __restrict__ W_end,
                            const float* __restrict__ b_end,
                            const float* __restrict__ W_hcw,
                            const float* __restrict__ b_hcw,
                            const float* __restrict__ W_roo,
                            const float* __restrict__ b_roo) {
    int idx = blockIdx.x * blockDim.x + threadIdx.x;
    const int total = NCOLS * HDIM;
    for (int i = idx; i < total; i += gridDim.x * blockDim.x) {
        int row = i >> 11;           // /2048
        int k   = i & (HDIM - 1);
        float v;
        if (row == 0)            v = W_end[k];
        else if (row <= FPN)     v = W_hcw[(size_t)(row - 1) * HDIM + k];
        else                     v = W_roo[(size_t)(row - 1 - FPN) * HDIM + k];
        g_W[i] = v;
    }
    if (idx < NCOLS) {
        float b;
        if (idx == 0)        b = b_end[0];
        else if (idx <= FPN) b = b_hcw[idx - 1];
        else                 b = b_roo[idx - 1 - FPN];
        g_bias[idx] = b;
    }
}

// ---------------------------------------------------------------------------
// SGEMM: g_C[n, c] = sum_k X[n,k] * g_W[c,k] + g_bias[c]
// Classic 128x128 tile, BK=16, 8x8 per thread, 256 threads.
// ---------------------------------------------------------------------------
#define BM 128
#define BN 128
#define BK 16
#define TM 8
#define TN 8
#define SPAD 4   // smem row pitch 132 floats (132*4 bytes, 16B-aligned rows)

__global__ __launch_bounds__(256, 2)
void sgemm_kernel(const float* __restrict__ X) {
    __shared__ float Xs[BK][BM + SPAD];
    __shared__ float Ws[BK][BN + SPAD];

    const int tid = threadIdx.x;
    const int tx = tid & 15;       // 0..15 -> column group
    const int ty = tid >> 4;       // 0..15 -> row group
    const int rowBase = blockIdx.y * BM;
    const int colBase = blockIdx.x * BN;

    float acc[TM][TN];
#pragma unroll
    for (int i = 0; i < TM; i++)
#pragma unroll
        for (int j = 0; j < TN; j++) acc[i][j] = 0.f;

    const float* Xg = X + (size_t)rowBase * HDIM;

    for (int k0 = 0; k0 < HDIM; k0 += BK) {
        // Load X tile: 128 rows x 16 k, transposed into Xs[k][row]
#pragma unroll
        for (int t = 0; t < 2; t++) {
            int idx = tid + t * 256;       // float4 slot 0..511
            int r   = idx >> 2;            // row in tile
            int kc  = (idx & 3) * 4;       // k offset
            float4 v = *reinterpret_cast<const float4*>(Xg + (size_t)r * HDIM + k0 + kc);
            Xs[kc + 0][r] = v.x;
            Xs[kc + 1][r] = v.y;
            Xs[kc + 2][r] = v.z;
            Xs[kc + 3][r] = v.w;
        }
        // Load W tile with column bound guard
#pragma unroll
        for (int t = 0; t < 2; t++) {
            int idx = tid + t * 256;
            int r   = idx >> 2;
            int kc  = (idx & 3) * 4;
            int wrow = colBase + r;
            float4 v = make_float4(0.f, 0.f, 0.f, 0.f);
            if (wrow < NCOLS)
                v = *reinterpret_cast<const float4*>(g_W + (size_t)wrow * HDIM + k0 + kc);
            Ws[kc + 0][r] = v.x;
            Ws[kc + 1][r] = v.y;
            Ws[kc + 2][r] = v.z;
            Ws[kc + 3][r] = v.w;
        }
        __syncthreads();

#pragma unroll
        for (int k = 0; k < BK; k++) {
            float4 a0 = *reinterpret_cast<const float4*>(&Xs[k][ty * TM]);
            float4 a1 = *reinterpret_cast<const float4*>(&Xs[k][ty * TM + 4]);
            float4 b0 = *reinterpret_cast<const float4*>(&Ws[k][tx * TN]);
            float4 b1 = *reinterpret_cast<const float4*>(&Ws[k][tx * TN + 4]);
            float a[8] = {a0.x, a0.y, a0.z, a0.w, a1.x, a1.y, a1.z, a1.w};
            float b[8] = {b0.x, b0.y, b0.z, b0.w, b1.x, b1.y, b1.z, b1.w};
#pragma unroll
            for (int i = 0; i < TM; i++)
#pragma unroll
                for (int j = 0; j < TN; j++)
                    acc[i][j] = fmaf(a[i], b[j], acc[i][j]);
        }
        __syncthreads();
    }

    // Store with bias folded in
#pragma unroll
    for (int i = 0; i < TM; i++) {
        int row = rowBase + ty * TM + i;
#pragma unroll
        for (int j = 0; j < TN; j++) {
            int col = colBase + tx * TN + j;
            if (col < NCOLS)
                g_C[(size_t)row * C_LD + col] = acc[i][j] + g_bias[col];
        }
    }
}

// ---------------------------------------------------------------------------
// Epilogue: per-token sigmoid + two softmaxes + gather + masked scatter.
// One CTA (256 threads) per token.
// Output layout: out[0 .. NTOK) = log_prob, then [NTOK ..) prob_all [NTOK, 2050].
// ---------------------------------------------------------------------------
__global__ __launch_bounds__(256)
void epilogue_kernel(const int* __restrict__ pY, const int* __restrict__ Yv,
                     float* __restrict__ out) {
    const int n = blockIdx.x;
    const float* Crow = g_C + (size_t)n * C_LD;
    __shared__ float sm[FPN + SPN];
    __shared__ float red[16];
    const int tid = threadIdx.x;
    const int lane = tid & 31, warp = tid >> 5;

    // Load hcw+roo logits (bias already folded)
    for (int j = tid; j < FPN + SPN; j += 256) sm[j] = Crow[1 + j];
    __syncthreads();

    // Max reductions for both softmaxes
    float mh = -INFINITY, mr = -INFINITY;
    for (int j = tid; j < FPN; j += 256) mh = fmaxf(mh, sm[j]);
    for (int j = tid; j < SPN; j += 256) mr = fmaxf(mr, sm[FPN + j]);
#pragma unroll
    for (int o = 16; o > 0; o >>= 1) {
        mh = fmaxf(mh, __shfl_xor_sync(0xffffffffu, mh, o));
        mr = fmaxf(mr, __shfl_xor_sync(0xffffffffu, mr, o));
    }
    if (lane == 0) { red[warp] = mh; red[8 + warp] = mr; }
    __syncthreads();
    mh = red[0]; mr = red[8];
#pragma unroll
    for (int w = 1; w < 8; w++) {
        mh = fmaxf(mh, red[w]);
        mr = fmaxf(mr, red[8 + w]);
    }

    // Exp + sum (store exp back into smem)
    float sh = 0.f, sr = 0.f;
    for (int j = tid; j < FPN; j += 256) { float e = expf(sm[j] - mh); sm[j] = e; sh += e; }
    for (int j = tid; j < SPN; j += 256) { float e = expf(sm[FPN + j] - mr); sm[FPN + j] = e; sr += e; }
#pragma unroll
    for (int o = 16; o > 0; o >>= 1) {
        sh += __shfl_xor_sync(0xffffffffu, sh, o);
        sr += __shfl_xor_sync(0xffffffffu, sr, o);
    }
    __syncthreads();          // smem exp writes complete; safe to reuse red
    if (lane == 0) { red[warp] = sh; red[8 + warp] = sr; }
    __syncthreads();
    sh = 0.f; sr = 0.f;
#pragma unroll
    for (int w = 0; w < 8; w++) { sh += red[w]; sr += red[8 + w]; }

    const float inv_sh = 1.f / sh;
    const float inv_sr = 1.f / sr;
    const float end_logit = Crow[0];
    const float end_prob = 1.f / (1.f + expf(-end_logit));
    const float non_end = 1.f - end_prob;

    const int t = pY[n];

    // prob_all row write (masked)
    float* orow = out + NTOK + (size_t)n * OUT_COLS;
    const float fe = (t == 0) ? end_prob : 0.f;
    const float fh = (t == 1) ? non_end * inv_sh : 0.f;
    const float fr = (t == 2) ? non_end * inv_sr : 0.f;
    for (int j = tid; j < OUT_COLS; j += 256) {
        float v;
        if (j < 2)              v = fe;
        else if (j < 2 + FPN)   v = sm[j - 2] * fh;
        else                    v = sm[j - 2] * fr;   // sm index in [FPN, FPN+SPN)
        orow[j] = v;
    }

    // log_prob scalar
    if (tid == 0) {
        const int y = Yv[n];
        float prob;
        if (t == 0) {
            prob = end_prob;
        } else if (t == 1) {
            int idx = y - 2; idx = idx < 0 ? 0 : (idx > FPN - 1 ? FPN - 1 : idx);
            prob = sm[idx] * inv_sh * non_end;
        } else if (t == 2) {
            int idx = y - 2 - FPN; idx = idx < 0 ? 0 : (idx > SPN - 1 ? SPN - 1 : idx);
            prob = sm[FPN + idx] * inv_sr * non_end;
        } else {
            prob = 1.f;
        }
        out[n] = logf(prob);
    }
}

// ---------------------------------------------------------------------------
// Launch
// ---------------------------------------------------------------------------
extern "C" void kernel_launch(void* const* d_in, const int* in_sizes, int n_in,
                              void* d_out, int out_size) {
    const float* X     = (const float*)d_in[0];
    const int*   pY    = (const int*)d_in[1];
    const int*   Yv    = (const int*)d_in[2];
    const float* W_end = (const float*)d_in[3];
    const float* b_end = (const float*)d_in[4];
    const float* W_hcw = (const float*)d_in[5];
    const float* b_hcw = (const float*)d_in[6];
    const float* W_roo = (const float*)d_in[7];
    const float* b_roo = (const float*)d_in[8];
    float* out = (float*)d_out;

    pack_kernel<<<4096, 256>>>(W_end, b_end, W_hcw, b_hcw, W_roo, b_roo);

    dim3 grid((NCOLS + BN - 1) / BN, NTOK / BM);   // 17 x 128
    sgemm_kernel<<<grid, 256>>>(X);

    epilogue_kernel<<<NTOK, 256>>>(pY, Yv, out);
}

// round 6
// speedup vs baseline: 1.9754x; 1.9754x over previous
#include <cuda_runtime.h>
#include <cuda_bf16.h>
#include <stdint.h>
#include <math.h>

// ---------------------------------------------------------------------------
// Problem constants
// ---------------------------------------------------------------------------
#define NTOK 16384      // B*S
#define HDIM 2048
#define FPN  1024
#define SPN  1024
#define NCOLS 2049      // 1 + FP + SP
#define NPAD  2304      // 18 * 128 (padded N for GEMM)
#define C_LD  2304
#define OUT_COLS 2050

// GEMM tiling (mma.sync m16n8k16, 8 warps, warp tile 64x32)
#define BM 128
#define BN 128
#define BK 16
#define NUM_CHUNKS (HDIM / BK)       // 128
#define KSTRIDE 24                   // padded bf16 elems per smem row (48B)
#define MAT_BYTES (128 * KSTRIDE * 2)    // 6144 per matrix tile
#define STAGE_BYTES (4 * MAT_BYTES)      // Ah|Al|Bh|Bl = 24576
// total static smem: 2 * STAGE_BYTES = 49152 (exactly 48KB)

// ---------------------------------------------------------------------------
// Device scratch (allocation-free rule: __device__ globals)
// ---------------------------------------------------------------------------
__device__ __align__(128) __nv_bfloat16 g_Xhi[(size_t)NTOK * HDIM];
__device__ __align__(128) __nv_bfloat16 g_Xlo[(size_t)NTOK * HDIM];
__device__ __align__(128) __nv_bfloat16 g_Whi[(size_t)NPAD * HDIM];
__device__ __align__(128) __nv_bfloat16 g_Wlo[(size_t)NPAD * HDIM];
__device__ float g_bias[NPAD];
__device__ __align__(128) float g_C[(size_t)NTOK * C_LD];

// ---------------------------------------------------------------------------
// Convert X -> bf16 hi/lo
// ---------------------------------------------------------------------------
__global__ void convert_x_kernel(const float* __restrict__ X) {
    const size_t total = (size_t)NTOK * HDIM / 4;
    for (size_t i = blockIdx.x * (size_t)blockDim.x + threadIdx.x; i < total;
         i += (size_t)gridDim.x * blockDim.x) {
        float4 v = ((const float4*)X)[i];
        float f[4] = {v.x, v.y, v.z, v.w};
        __nv_bfloat16 h[4], l[4];
#pragma unroll
        for (int j = 0; j < 4; j++) {
            h[j] = __float2bfloat16(f[j]);
            l[j] = __float2bfloat16(f[j] - __bfloat162float(h[j]));
        }
        ((uint2*)g_Xhi)[i] = *(uint2*)h;
        ((uint2*)g_Xlo)[i] = *(uint2*)l;
    }
}

// ---------------------------------------------------------------------------
// Pack W_end/W_hcw/W_roo -> bf16 hi/lo [NPAD, HDIM], zero padded + bias
// ---------------------------------------------------------------------------
__global__ void pack_w_kernel(const float* __restrict__ W_end,
                              const float* __restrict__ b_end,
                              const float* __restrict__ W_hcw,
                              const float* __restrict__ b_hcw,
                              const float* __restrict__ W_roo,
                              const float* __restrict__ b_roo) {
    const size_t total = (size_t)NPAD * HDIM / 4;
    for (size_t i = blockIdx.x * (size_t)blockDim.x + threadIdx.x; i < total;
         i += (size_t)gridDim.x * blockDim.x) {
        size_t e = i * 4;
        int row = (int)(e >> 11);
        int k   = (int)(e & (HDIM - 1));
        float4 v = make_float4(0.f, 0.f, 0.f, 0.f);
        if (row == 0)            v = *(const float4*)(W_end + k);
        else if (row <= FPN)     v = *(const float4*)(W_hcw + (size_t)(row - 1) * HDIM + k);
        else if (row < NCOLS)    v = *(const float4*)(W_roo + (size_t)(row - 1 - FPN) * HDIM + k);
        float f[4] = {v.x, v.y, v.z, v.w};
        __nv_bfloat16 h[4], l[4];
#pragma unroll
        for (int j = 0; j < 4; j++) {
            h[j] = __float2bfloat16(f[j]);
            l[j] = __float2bfloat16(f[j] - __bfloat162float(h[j]));
        }
        ((uint2*)g_Whi)[i] = *(uint2*)h;
        ((uint2*)g_Wlo)[i] = *(uint2*)l;
    }
    int idx = blockIdx.x * blockDim.x + threadIdx.x;
    if (idx < NPAD) {
        float b = 0.f;
        if (idx == 0)         b = b_end[0];
        else if (idx <= FPN)  b = b_hcw[idx - 1];
        else if (idx < NCOLS) b = b_roo[idx - 1 - FPN];
        g_bias[idx] = b;
    }
}

// ---------------------------------------------------------------------------
// mma.sync helpers
// ---------------------------------------------------------------------------
__device__ __forceinline__ void mma16816(float* c, const uint32_t* a,
                                         const uint32_t* b) {
    asm volatile(
        "mma.sync.aligned.m16n8k16.row.col.f32.bf16.bf16.f32 "
        "{%0,%1,%2,%3}, {%4,%5,%6,%7}, {%8,%9}, {%0,%1,%2,%3};"
        : "+f"(c[0]), "+f"(c[1]), "+f"(c[2]), "+f"(c[3])
        : "r"(a[0]), "r"(a[1]), "r"(a[2]), "r"(a[3]), "r"(b[0]), "r"(b[1]));
}

// ---------------------------------------------------------------------------
// GEMM: g_C[m, n] = sum_k (Xhi+Xlo)[m,k] * (Whi+Wlo)[n,k] + bias[n]
// 3-term bf16 split via mma.sync; cp.async double buffer; 48KB static smem.
// ---------------------------------------------------------------------------
__global__ void __launch_bounds__(256, 1) gemm_kernel() {
    __shared__ __align__(16) char sm[2 * STAGE_BYTES];

    const int tid  = threadIdx.x;
    const int wid  = tid >> 5;
    const int lane = tid & 31;
    const int wm   = wid & 1;      // 2 warp rows  (64 M each)
    const int wn   = wid >> 1;     // 4 warp cols  (32 N each)
    const int g    = lane >> 2;    // group id 0..7
    const int t    = lane & 3;     // thread-in-group 0..3
    const int mBase = blockIdx.y * BM;
    const int nBase = blockIdx.x * BN;

    const uint32_t smu = (uint32_t)__cvta_generic_to_shared(sm);

    // Stage loader: 1024 x 16B chunks, 4 per thread.
    auto load_stage = [&](int buf, int k0) {
#pragma unroll
        for (int tt = 0; tt < 4; tt++) {
            int id   = tid + tt * 256;        // 0..1023
            int mat  = id >> 8;               // 0:Ah 1:Al 2:Bh 3:Bl
            int ci   = id & 255;
            int row  = ci >> 1;
            int half = ci & 1;                // k sub-offset 0 / 8
            const __nv_bfloat16* gp =
                (mat == 0) ? g_Xhi : (mat == 1) ? g_Xlo
                : (mat == 2) ? g_Whi : g_Wlo;
            int grow = ((mat < 2) ? mBase : nBase) + row;
            const __nv_bfloat16* src =
                gp + (size_t)grow * HDIM + k0 + half * 8;
            uint32_t dst = smu + (uint32_t)(buf * STAGE_BYTES + mat * MAT_BYTES +
                                            row * (KSTRIDE * 2) + half * 16);
            asm volatile("cp.async.cg.shared.global [%0], [%1], 16;\n"
                         :: "r"(dst), "l"(src) : "memory");
        }
        asm volatile("cp.async.commit_group;" ::: "memory");
    };

    float acc[4][4][4];
#pragma unroll
    for (int i = 0; i < 4; i++)
#pragma unroll
        for (int j = 0; j < 4; j++)
#pragma unroll
            for (int q = 0; q < 4; q++) acc[i][j][q] = 0.f;

    load_stage(0, 0);
    load_stage(1, BK);

    for (int c = 0; c < NUM_CHUNKS; c++) {
        if (c >= NUM_CHUNKS - 2)
            asm volatile("cp.async.wait_group 0;" ::: "memory");
        else
            asm volatile("cp.async.wait_group 1;" ::: "memory");
        __syncthreads();

        const char* stage = sm + (c & 1) * STAGE_BYTES;
        const __nv_bfloat16* Ah = (const __nv_bfloat16*)(stage + 0 * MAT_BYTES);
        const __nv_bfloat16* Al = (const __nv_bfloat16*)(stage + 1 * MAT_BYTES);
        const __nv_bfloat16* Bh = (const __nv_bfloat16*)(stage + 2 * MAT_BYTES);
        const __nv_bfloat16* Bl = (const __nv_bfloat16*)(stage + 3 * MAT_BYTES);

        uint32_t ah[4][4], al[4][4], bh[4][2], bl[4][2];
#pragma unroll
        for (int mi = 0; mi < 4; mi++) {
            int r0 = (wm * 64 + mi * 16 + g) * KSTRIDE;
            int r1 = r0 + 8 * KSTRIDE;
            ah[mi][0] = *(const uint32_t*)(Ah + r0 + t * 2);
            ah[mi][1] = *(const uint32_t*)(Ah + r1 + t * 2);
            ah[mi][2] = *(const uint32_t*)(Ah + r0 + t * 2 + 8);
            ah[mi][3] = *(const uint32_t*)(Ah + r1 + t * 2 + 8);
            al[mi][0] = *(const uint32_t*)(Al + r0 + t * 2);
            al[mi][1] = *(const uint32_t*)(Al + r1 + t * 2);
            al[mi][2] = *(const uint32_t*)(Al + r0 + t * 2 + 8);
            al[mi][3] = *(const uint32_t*)(Al + r1 + t * 2 + 8);
        }
#pragma unroll
        for (int nj = 0; nj < 4; nj++) {
            int rn = (wn * 32 + nj * 8 + g) * KSTRIDE;
            bh[nj][0] = *(const uint32_t*)(Bh + rn + t * 2);
            bh[nj][1] = *(const uint32_t*)(Bh + rn + t * 2 + 8);
            bl[nj][0] = *(const uint32_t*)(Bl + rn + t * 2);
            bl[nj][1] = *(const uint32_t*)(Bl + rn + t * 2 + 8);
        }

#pragma unroll
        for (int mi = 0; mi < 4; mi++)
#pragma unroll
            for (int nj = 0; nj < 4; nj++)
                mma16816(acc[mi][nj], ah[mi], bh[nj]);
#pragma unroll
        for (int mi = 0; mi < 4; mi++)
#pragma unroll
            for (int nj = 0; nj < 4; nj++)
                mma16816(acc[mi][nj], ah[mi], bl[nj]);
#pragma unroll
        for (int mi = 0; mi < 4; mi++)
#pragma unroll
            for (int nj = 0; nj < 4; nj++)
                mma16816(acc[mi][nj], al[mi], bh[nj]);

        __syncthreads();
        if (c + 2 < NUM_CHUNKS) load_stage(c & 1, (c + 2) * BK);
    }

    // Store accumulators + bias to g_C
#pragma unroll
    for (int mi = 0; mi < 4; mi++) {
        int m0 = mBase + wm * 64 + mi * 16 + g;
#pragma unroll
        for (int nj = 0; nj < 4; nj++) {
            int col = nBase + wn * 32 + nj * 8 + t * 2;
            float b0 = g_bias[col];
            float b1 = g_bias[col + 1];
            float2 v0 = make_float2(acc[mi][nj][0] + b0, acc[mi][nj][1] + b1);
            float2 v1 = make_float2(acc[mi][nj][2] + b0, acc[mi][nj][3] + b1);
            *(float2*)(g_C + (size_t)m0 * C_LD + col) = v0;
            *(float2*)(g_C + (size_t)(m0 + 8) * C_LD + col) = v1;
        }
    }
}

// ---------------------------------------------------------------------------
// Epilogue: per-token sigmoid + two softmaxes + gather + masked scatter.
// ---------------------------------------------------------------------------
__global__ __launch_bounds__(256)
void epilogue_kernel(const int* __restrict__ pY, const int* __restrict__ Yv,
                     float* __restrict__ out) {
    const int n = blockIdx.x;
    const float* Crow = g_C + (size_t)n * C_LD;
    __shared__ float sm[FPN + SPN];
    __shared__ float red[16];
    const int tid = threadIdx.x;
    const int lane = tid & 31, warp = tid >> 5;

    for (int j = tid; j < FPN + SPN; j += 256) sm[j] = Crow[1 + j];
    __syncthreads();

    float mh = -INFINITY, mr = -INFINITY;
    for (int j = tid; j < FPN; j += 256) mh = fmaxf(mh, sm[j]);
    for (int j = tid; j < SPN; j += 256) mr = fmaxf(mr, sm[FPN + j]);
#pragma unroll
    for (int o = 16; o > 0; o >>= 1) {
        mh = fmaxf(mh, __shfl_xor_sync(0xffffffffu, mh, o));
        mr = fmaxf(mr, __shfl_xor_sync(0xffffffffu, mr, o));
    }
    if (lane == 0) { red[warp] = mh; red[8 + warp] = mr; }
    __syncthreads();
    mh = red[0]; mr = red[8];
#pragma unroll
    for (int w = 1; w < 8; w++) {
        mh = fmaxf(mh, red[w]);
        mr = fmaxf(mr, red[8 + w]);
    }

    float sh = 0.f, sr = 0.f;
    for (int j = tid; j < FPN; j += 256) { float e = expf(sm[j] - mh); sm[j] = e; sh += e; }
    for (int j = tid; j < SPN; j += 256) { float e = expf(sm[FPN + j] - mr); sm[FPN + j] = e; sr += e; }
#pragma unroll
    for (int o = 16; o > 0; o >>= 1) {
        sh += __shfl_xor_sync(0xffffffffu, sh, o);
        sr += __shfl_xor_sync(0xffffffffu, sr, o);
    }
    __syncthreads();
    if (lane == 0) { red[warp] = sh; red[8 + warp] = sr; }
    __syncthreads();
    sh = 0.f; sr = 0.f;
#pragma unroll
    for (int w = 0; w < 8; w++) { sh += red[w]; sr += red[8 + w]; }

    const float inv_sh = 1.f / sh;
    const float inv_sr = 1.f / sr;
    const float end_logit = Crow[0];
    const float end_prob = 1.f / (1.f + expf(-end_logit));
    const float non_end = 1.f - end_prob;

    const int ty = pY[n];

    float* orow = out + NTOK + (size_t)n * OUT_COLS;
    const float fe = (ty == 0) ? end_prob : 0.f;
    const float fh = (ty == 1) ? non_end * inv_sh : 0.f;
    const float fr = (ty == 2) ? non_end * inv_sr : 0.f;
    for (int j = tid; j < OUT_COLS; j += 256) {
        float v;
        if (j < 2)            v = fe;
        else if (j < 2 + FPN) v = sm[j - 2] * fh;
        else                  v = sm[j - 2] * fr;
        orow[j] = v;
    }

    if (tid == 0) {
        const int y = Yv[n];
        float prob;
        if (ty == 0) {
            prob = end_prob;
        } else if (ty == 1) {
            int idx = y - 2; idx = idx < 0 ? 0 : (idx > FPN - 1 ? FPN - 1 : idx);
            prob = sm[idx] * inv_sh * non_end;
        } else if (ty == 2) {
            int idx = y - 2 - FPN; idx = idx < 0 ? 0 : (idx > SPN - 1 ? SPN - 1 : idx);
            prob = sm[FPN + idx] * inv_sr * non_end;
        } else {
            prob = 1.f;
        }
        out[n] = logf(prob);
    }
}

// ---------------------------------------------------------------------------
// Launch
// ---------------------------------------------------------------------------
extern "C" void kernel_launch(void* const* d_in, const int* in_sizes, int n_in,
                              void* d_out, int out_size) {
    const float* X     = (const float*)d_in[0];
    const int*   pY    = (const int*)d_in[1];
    const int*   Yv    = (const int*)d_in[2];
    const float* W_end = (const float*)d_in[3];
    const float* b_end = (const float*)d_in[4];
    const float* W_hcw = (const float*)d_in[5];
    const float* b_hcw = (const float*)d_in[6];
    const float* W_roo = (const float*)d_in[7];
    const float* b_roo = (const float*)d_in[8];
    float* out = (float*)d_out;

    convert_x_kernel<<<2048, 256>>>(X);
    pack_w_kernel<<<2048, 256>>>(W_end, b_end, W_hcw, b_hcw, W_roo, b_roo);

    dim3 grid(NPAD / BN, NTOK / BM);   // (18, 128)
    gemm_kernel<<<grid, 256>>>();

    epilogue_kernel<<<NTOK, 256>>>(pY, Yv, out);
}

// round 9
// speedup vs baseline: 2.8884x; 1.4622x over previous
#include <cuda_runtime.h>
#include <cuda_fp16.h>
#include <stdint.h>
#include <math.h>

// ---------------------------------------------------------------------------
// Problem constants
// ---------------------------------------------------------------------------
#define NTOK 16384      // B*S
#define HDIM 2048
#define FPN  1024
#define SPN  1024
#define NCOLS 2049      // 1 + FP + SP
#define NPAD  2304      // padded rows in packed W (zero-filled)
#define NTILES 16       // 16 * 128 = 2048 cols; col 2048 done by lastcol_kernel
#define C_LD  2304
#define OUT_COLS 2050

// GEMM tiling (mma.sync m16n8k16, 8 warps, warp tile 64x32)
#define BM 128
#define BN 128
#define BK 16
#define NUM_CHUNKS (HDIM / BK)       // 128
#define KSTRIDE 24                   // padded fp16 elems per smem row (48B)
#define MAT_BYTES (128 * KSTRIDE * 2)    // 6144 per matrix tile
#define STAGE_BYTES (3 * MAT_BYTES)      // Ah|Al|B = 18432
// total static smem: 2 * STAGE_BYTES = 36864

// ---------------------------------------------------------------------------
// Device scratch (allocation-free rule: __device__ globals)
// ---------------------------------------------------------------------------
__device__ __align__(128) __half g_Xhi[(size_t)NTOK * HDIM];
__device__ __align__(128) __half g_Xlo[(size_t)NTOK * HDIM];
__device__ __align__(128) __half g_W[(size_t)NPAD * HDIM];
__device__ float g_bias[NPAD];
__device__ __align__(128) float g_C[(size_t)NTOK * C_LD];

// ---------------------------------------------------------------------------
// Convert X -> fp16 hi/lo (hi + lo captures ~22 mantissa bits of fp32)
// ---------------------------------------------------------------------------
__global__ void convert_x_kernel(const float* __restrict__ X) {
    const size_t total = (size_t)NTOK * HDIM / 4;
    for (size_t i = blockIdx.x * (size_t)blockDim.x + threadIdx.x; i < total;
         i += (size_t)gridDim.x * blockDim.x) {
        float4 v = ((const float4*)X)[i];
        float f[4] = {v.x, v.y, v.z, v.w};
        __half h[4], l[4];
#pragma unroll
        for (int j = 0; j < 4; j++) {
            h[j] = __float2half(f[j]);
            l[j] = __float2half(f[j] - __half2float(h[j]));
        }
        ((uint2*)g_Xhi)[i] = *(uint2*)h;
        ((uint2*)g_Xlo)[i] = *(uint2*)l;
    }
}

// ---------------------------------------------------------------------------
// Pack W_end/W_hcw/W_roo -> single fp16 [NPAD, HDIM], zero padded + bias
// ---------------------------------------------------------------------------
__global__ void pack_w_kernel(const float* __restrict__ W_end,
                              const float* __restrict__ b_end,
                              const float* __restrict__ W_hcw,
                              const float* __restrict__ b_hcw,
                              const float* __restrict__ W_roo,
                              const float* __restrict__ b_roo) {
    const size_t total = (size_t)NPAD * HDIM / 4;
    for (size_t i = blockIdx.x * (size_t)blockDim.x + threadIdx.x; i < total;
         i += (size_t)gridDim.x * blockDim.x) {
        size_t e = i * 4;
        int row = (int)(e >> 11);
        int k   = (int)(e & (HDIM - 1));
        float4 v = make_float4(0.f, 0.f, 0.f, 0.f);
        if (row == 0)            v = *(const float4*)(W_end + k);
        else if (row <= FPN)     v = *(const float4*)(W_hcw + (size_t)(row - 1) * HDIM + k);
        else if (row < NCOLS)    v = *(const float4*)(W_roo + (size_t)(row - 1 - FPN) * HDIM + k);
        __half h[4];
        h[0] = __float2half(v.x);
        h[1] = __float2half(v.y);
        h[2] = __float2half(v.z);
        h[3] = __float2half(v.w);
        ((uint2*)g_W)[i] = *(uint2*)h;
    }
    int idx = blockIdx.x * blockDim.x + threadIdx.x;
    if (idx < NPAD) {
        float b = 0.f;
        if (idx == 0)         b = b_end[0];
        else if (idx <= FPN)  b = b_hcw[idx - 1];
        else if (idx < NCOLS) b = b_roo[idx - 1 - FPN];
        g_bias[idx] = b;
    }
}

// ---------------------------------------------------------------------------
// mma.sync helper (fp16 in, fp32 accumulate)
// ---------------------------------------------------------------------------
__device__ __forceinline__ void mma16816(float* c, const uint32_t* a,
                                         const uint32_t* b) {
    asm volatile(
        "mma.sync.aligned.m16n8k16.row.col.f32.f16.f16.f32 "
        "{%0,%1,%2,%3}, {%4,%5,%6,%7}, {%8,%9}, {%0,%1,%2,%3};"
        : "+f"(c[0]), "+f"(c[1]), "+f"(c[2]), "+f"(c[3])
        : "r"(a[0]), "r"(a[1]), "r"(a[2]), "r"(a[3]), "r"(b[0]), "r"(b[1]));
}

// ---------------------------------------------------------------------------
// GEMM: g_C[m, n] = sum_k (Xhi+Xlo)[m,k] * W[n,k] + bias[n]   (2 MMA terms)
// ---------------------------------------------------------------------------
__global__ void __launch_bounds__(256, 1) gemm_kernel() {
    __shared__ __align__(16) char sm[2 * STAGE_BYTES];

    const int tid  = threadIdx.x;
    const int wid  = tid >> 5;
    const int lane = tid & 31;
    const int wm   = wid & 1;      // 2 warp rows  (64 M each)
    const int wn   = wid >> 1;     // 4 warp cols  (32 N each)
    const int g    = lane >> 2;    // group id 0..7
    const int t    = lane & 3;     // thread-in-group 0..3
    const int mBase = blockIdx.y * BM;
    const int nBase = blockIdx.x * BN;

    const uint32_t smu = (uint32_t)__cvta_generic_to_shared(sm);

    // Stage loader: 768 x 16B chunks, 3 per thread.
    auto load_stage = [&](int buf, int k0) {
#pragma unroll
        for (int tt = 0; tt < 3; tt++) {
            int id   = tid + tt * 256;        // 0..767
            int mat  = id >> 8;               // 0:Ah 1:Al 2:B
            int ci   = id & 255;
            int row  = ci >> 1;
            int half = ci & 1;                // k sub-offset 0 / 8
            const __half* gp =
                (mat == 0) ? g_Xhi : (mat == 1) ? g_Xlo : g_W;
            int grow = ((mat < 2) ? mBase : nBase) + row;
            const __half* src = gp + (size_t)grow * HDIM + k0 + half * 8;
            uint32_t dst = smu + (uint32_t)(buf * STAGE_BYTES + mat * MAT_BYTES +
                                            row * (KSTRIDE * 2) + half * 16);
            asm volatile("cp.async.cg.shared.global [%0], [%1], 16;\n"
                         :: "r"(dst), "l"(src) : "memory");
        }
        asm volatile("cp.async.commit_group;" ::: "memory");
    };

    float acc[4][4][4];
#pragma unroll
    for (int i = 0; i < 4; i++)
#pragma unroll
        for (int j = 0; j < 4; j++)
#pragma unroll
            for (int q = 0; q < 4; q++) acc[i][j][q] = 0.f;

    load_stage(0, 0);
    load_stage(1, BK);

    for (int c = 0; c < NUM_CHUNKS; c++) {
        if (c >= NUM_CHUNKS - 2)
            asm volatile("cp.async.wait_group 0;" ::: "memory");
        else
            asm volatile("cp.async.wait_group 1;" ::: "memory");
        __syncthreads();

        const char* stage = sm + (c & 1) * STAGE_BYTES;
        const __half* Ah = (const __half*)(stage + 0 * MAT_BYTES);
        const __half* Al = (const __half*)(stage + 1 * MAT_BYTES);
        const __half* Bm = (const __half*)(stage + 2 * MAT_BYTES);

        uint32_t ah[4][4], al[4][4], bb[4][2];
#pragma unroll
        for (int mi = 0; mi < 4; mi++) {
            int r0 = (wm * 64 + mi * 16 + g) * KSTRIDE;
            int r1 = r0 + 8 * KSTRIDE;
            ah[mi][0] = *(const uint32_t*)(Ah + r0 + t * 2);
            ah[mi][1] = *(const uint32_t*)(Ah + r1 + t * 2);
            ah[mi][2] = *(const uint32_t*)(Ah + r0 + t * 2 + 8);
            ah[mi][3] = *(const uint32_t*)(Ah + r1 + t * 2 + 8);
            al[mi][0] = *(const uint32_t*)(Al + r0 + t * 2);
            al[mi][1] = *(const uint32_t*)(Al + r1 + t * 2);
            al[mi][2] = *(const uint32_t*)(Al + r0 + t * 2 + 8);
            al[mi][3] = *(const uint32_t*)(Al + r1 + t * 2 + 8);
        }
#pragma unroll
        for (int nj = 0; nj < 4; nj++) {
            int rn = (wn * 32 + nj * 8 + g) * KSTRIDE;
            bb[nj][0] = *(const uint32_t*)(Bm + rn + t * 2);
            bb[nj][1] = *(const uint32_t*)(Bm + rn + t * 2 + 8);
        }

#pragma unroll
        for (int mi = 0; mi < 4; mi++)
#pragma unroll
            for (int nj = 0; nj < 4; nj++)
                mma16816(acc[mi][nj], ah[mi], bb[nj]);
#pragma unroll
        for (int mi = 0; mi < 4; mi++)
#pragma unroll
            for (int nj = 0; nj < 4; nj++)
                mma16816(acc[mi][nj], al[mi], bb[nj]);

        __syncthreads();
        if (c + 2 < NUM_CHUNKS) load_stage(c & 1, (c + 2) * BK);
    }

    // Store accumulators + bias to g_C
#pragma unroll
    for (int mi = 0; mi < 4; mi++) {
        int m0 = mBase + wm * 64 + mi * 16 + g;
#pragma unroll
        for (int nj = 0; nj < 4; nj++) {
            int col = nBase + wn * 32 + nj * 8 + t * 2;
            float b0 = g_bias[col];
            float b1 = g_bias[col + 1];
            float2 v0 = make_float2(acc[mi][nj][0] + b0, acc[mi][nj][1] + b1);
            float2 v1 = make_float2(acc[mi][nj][2] + b0, acc[mi][nj][3] + b1);
            *(float2*)(g_C + (size_t)m0 * C_LD + col) = v0;
            *(float2*)(g_C + (size_t)(m0 + 8) * C_LD + col) = v1;
        }
    }
}

// ---------------------------------------------------------------------------
// Last column (2048 = roo row 1023) in exact fp32: one warp per token.
// ---------------------------------------------------------------------------
__global__ __launch_bounds__(256)
void lastcol_kernel(const float* __restrict__ X,
                    const float* __restrict__ W_roo,
                    const float* __restrict__ b_roo) {
    __shared__ float w[HDIM];
    const int tid = threadIdx.x;
    for (int j = tid; j < HDIM; j += 256)
        w[j] = W_roo[(size_t)(SPN - 1) * HDIM + j];
    __syncthreads();

    const int warp = tid >> 5, lane = tid & 31;
    const int n = blockIdx.x * 8 + warp;
    const float* x = X + (size_t)n * HDIM;
    float s = 0.f;
    for (int j = lane * 4; j < HDIM; j += 128) {
        float4 v = *(const float4*)(x + j);
        float4 wv = *(const float4*)(w + j);
        s += v.x * wv.x + v.y * wv.y + v.z * wv.z + v.w * wv.w;
    }
#pragma unroll
    for (int o = 16; o > 0; o >>= 1) s += __shfl_xor_sync(0xffffffffu, s, o);
    if (lane == 0)
        g_C[(size_t)n * C_LD + 2048] = s + b_roo[SPN - 1];
}

// ---------------------------------------------------------------------------
// Epilogue: per-token sigmoid + two softmaxes + gather + masked scatter.
// ---------------------------------------------------------------------------
__global__ __launch_bounds__(256)
void epilogue_kernel(const int* __restrict__ pY, const int* __restrict__ Yv,
                     float* __restrict__ out) {
    const int n = blockIdx.x;
    const float* Crow = g_C + (size_t)n * C_LD;
    __shared__ float sm[FPN + SPN];
    __shared__ float red[16];
    const int tid = threadIdx.x;
    const int lane = tid & 31, warp = tid >> 5;

    for (int j = tid; j < FPN + SPN; j += 256) sm[j] = Crow[1 + j];
    __syncthreads();

    float mh = -INFINITY, mr = -INFINITY;
    for (int j = tid; j < FPN; j += 256) mh = fmaxf(mh, sm[j]);
    for (int j = tid; j < SPN; j += 256) mr = fmaxf(mr, sm[FPN + j]);
#pragma unroll
    for (int o = 16; o > 0; o >>= 1) {
        mh = fmaxf(mh, __shfl_xor_sync(0xffffffffu, mh, o));
        mr = fmaxf(mr, __shfl_xor_sync(0xffffffffu, mr, o));
    }
    if (lane == 0) { red[warp] = mh; red[8 + warp] = mr; }
    __syncthreads();
    mh = red[0]; mr = red[8];
#pragma unroll
    for (int w = 1; w < 8; w++) {
        mh = fmaxf(mh, red[w]);
        mr = fmaxf(mr, red[8 + w]);
    }

    float sh = 0.f, sr = 0.f;
    for (int j = tid; j < FPN; j += 256) { float e = expf(sm[j] - mh); sm[j] = e; sh += e; }
    for (int j = tid; j < SPN; j += 256) { float e = expf(sm[FPN + j] - mr); sm[FPN + j] = e; sr += e; }
#pragma unroll
    for (int o = 16; o > 0; o >>= 1) {
        sh += __shfl_xor_sync(0xffffffffu, sh, o);
        sr += __shfl_xor_sync(0xffffffffu, sr, o);
    }
    __syncthreads();
    if (lane == 0) { red[warp] = sh; red[8 + warp] = sr; }
    __syncthreads();
    sh = 0.f; sr = 0.f;
#pragma unroll
    for (int w = 0; w < 8; w++) { sh += red[w]; sr += red[8 + w]; }

    const float inv_sh = 1.f / sh;
    const float inv_sr = 1.f / sr;
    const float end_logit = Crow[0];
    const float end_prob = 1.f / (1.f + expf(-end_logit));
    const float non_end = 1.f - end_prob;

    const int ty = pY[n];

    float* orow = out + NTOK + (size_t)n * OUT_COLS;
    const float fe = (ty == 0) ? end_prob : 0.f;
    const float fh = (ty == 1) ? non_end * inv_sh : 0.f;
    const float fr = (ty == 2) ? non_end * inv_sr : 0.f;
    for (int j = tid; j < OUT_COLS; j += 256) {
        float v;
        if (j < 2)            v = fe;
        else if (j < 2 + FPN) v = sm[j - 2] * fh;
        else                  v = sm[j - 2] * fr;
        orow[j] = v;
    }

    if (tid == 0) {
        const int y = Yv[n];
        float prob;
        if (ty == 0) {
            prob = end_prob;
        } else if (ty == 1) {
            int idx = y - 2; idx = idx < 0 ? 0 : (idx > FPN - 1 ? FPN - 1 : idx);
            prob = sm[idx] * inv_sh * non_end;
        } else if (ty == 2) {
            int idx = y - 2 - FPN; idx = idx < 0 ? 0 : (idx > SPN - 1 ? SPN - 1 : idx);
            prob = sm[FPN + idx] * inv_sr * non_end;
        } else {
            prob = 1.f;
        }
        out[n] = logf(prob);
    }
}

// ---------------------------------------------------------------------------
// Launch
// ---------------------------------------------------------------------------
extern "C" void kernel_launch(void* const* d_in, const int* in_sizes, int n_in,
                              void* d_out, int out_size) {
    const float* X     = (const float*)d_in[0];
    const int*   pY    = (const int*)d_in[1];
    const int*   Yv    = (const int*)d_in[2];
    const float* W_end = (const float*)d_in[3];
    const float* b_end = (const float*)d_in[4];
    const float* W_hcw = (const float*)d_in[5];
    const float* b_hcw = (const float*)d_in[6];
    const float* W_roo = (const float*)d_in[7];
    const float* b_roo = (const float*)d_in[8];
    float* out = (float*)d_out;

    convert_x_kernel<<<2048, 256>>>(X);
    pack_w_kernel<<<2048, 256>>>(W_end, b_end, W_hcw, b_hcw, W_roo, b_roo);

    dim3 grid(NTILES, NTOK / BM);   // (16, 128) — cols 0..2047
    gemm_kernel<<<grid, 256>>>();

    lastcol_kernel<<<NTOK / 8, 256>>>(X, W_roo, b_roo);   // col 2048

    epilogue_kernel<<<NTOK, 256>>>(pY, Yv, out);
}

// round 10
// speedup vs baseline: 4.2822x; 1.4826x over previous
#include <cuda_runtime.h>
#include <cuda_fp16.h>
#include <stdint.h>
#include <math.h>

// ---------------------------------------------------------------------------
// Problem constants
// ---------------------------------------------------------------------------
#define NTOK 16384      // B*S
#define HDIM 2048
#define FPN  1024
#define SPN  1024
#define NCOLS 2049      // 1 + FP + SP
#define NPAD  2304      // padded rows in packed W (zero-filled)
#define NTILES 16       // 16 * 128 = 2048 cols; col 2048 done by lastcol_kernel
#define C_LD  2304
#define OUT_COLS 2050

// GEMM tiling (mma.sync m16n8k16, 8 warps, warp tile 64x32)
#define BM 128
#define BN 128
#define BK 16
#define NUM_CHUNKS (HDIM / BK)       // 128
#define KSTRIDE 24                   // padded fp16 elems per smem row (48B)
#define MAT_BYTES (128 * KSTRIDE * 2)    // 6144 per matrix tile
#define STAGE_BYTES (2 * MAT_BYTES)      // A|B = 12288
// total static smem: 2 * STAGE_BYTES = 24576

// ---------------------------------------------------------------------------
// Device scratch (allocation-free rule: __device__ globals)
// ---------------------------------------------------------------------------
__device__ __align__(128) __half g_Xh[(size_t)NTOK * HDIM];
__device__ __align__(128) __half g_W[(size_t)NPAD * HDIM];
__device__ float g_bias[NPAD];
__device__ __align__(128) float g_C[(size_t)NTOK * C_LD];

// ---------------------------------------------------------------------------
// Convert X -> fp16
// ---------------------------------------------------------------------------
__global__ void convert_x_kernel(const float* __restrict__ X) {
    const size_t total = (size_t)NTOK * HDIM / 4;
    for (size_t i = blockIdx.x * (size_t)blockDim.x + threadIdx.x; i < total;
         i += (size_t)gridDim.x * blockDim.x) {
        float4 v = ((const float4*)X)[i];
        __half h[4];
        h[0] = __float2half(v.x);
        h[1] = __float2half(v.y);
        h[2] = __float2half(v.z);
        h[3] = __float2half(v.w);
        ((uint2*)g_Xh)[i] = *(uint2*)h;
    }
}

// ---------------------------------------------------------------------------
// Pack W_end/W_hcw/W_roo -> single fp16 [NPAD, HDIM], zero padded + bias
// ---------------------------------------------------------------------------
__global__ void pack_w_kernel(const float* __restrict__ W_end,
                              const float* __restrict__ b_end,
                              const float* __restrict__ W_hcw,
                              const float* __restrict__ b_hcw,
                              const float* __restrict__ W_roo,
                              const float* __restrict__ b_roo) {
    const size_t total = (size_t)NPAD * HDIM / 4;
    for (size_t i = blockIdx.x * (size_t)blockDim.x + threadIdx.x; i < total;
         i += (size_t)gridDim.x * blockDim.x) {
        size_t e = i * 4;
        int row = (int)(e >> 11);
        int k   = (int)(e & (HDIM - 1));
        float4 v = make_float4(0.f, 0.f, 0.f, 0.f);
        if (row == 0)            v = *(const float4*)(W_end + k);
        else if (row <= FPN)     v = *(const float4*)(W_hcw + (size_t)(row - 1) * HDIM + k);
        else if (row < NCOLS)    v = *(const float4*)(W_roo + (size_t)(row - 1 - FPN) * HDIM + k);
        __half h[4];
        h[0] = __float2half(v.x);
        h[1] = __float2half(v.y);
        h[2] = __float2half(v.z);
        h[3] = __float2half(v.w);
        ((uint2*)g_W)[i] = *(uint2*)h;
    }
    int idx = blockIdx.x * blockDim.x + threadIdx.x;
    if (idx < NPAD) {
        float b = 0.f;
        if (idx == 0)         b = b_end[0];
        else if (idx <= FPN)  b = b_hcw[idx - 1];
        else if (idx < NCOLS) b = b_roo[idx - 1 - FPN];
        g_bias[idx] = b;
    }
}

// ---------------------------------------------------------------------------
// mma.sync helper (fp16 in, fp32 accumulate)
// ---------------------------------------------------------------------------
__device__ __forceinline__ void mma16816(float* c, const uint32_t* a,
                                         const uint32_t* b) {
    asm volatile(
        "mma.sync.aligned.m16n8k16.row.col.f32.f16.f16.f32 "
        "{%0,%1,%2,%3}, {%4,%5,%6,%7}, {%8,%9}, {%0,%1,%2,%3};"
        : "+f"(c[0]), "+f"(c[1]), "+f"(c[2]), "+f"(c[3])
        : "r"(a[0]), "r"(a[1]), "r"(a[2]), "r"(a[3]), "r"(b[0]), "r"(b[1]));
}

// ---------------------------------------------------------------------------
// GEMM: g_C[m, n] = sum_k Xh[m,k] * W[n,k] + bias[n]   (single fp16 term)
// ---------------------------------------------------------------------------
__global__ void __launch_bounds__(256, 1) gemm_kernel() {
    __shared__ __align__(16) char sm[2 * STAGE_BYTES];

    const int tid  = threadIdx.x;
    const int wid  = tid >> 5;
    const int lane = tid & 31;
    const int wm   = wid & 1;      // 2 warp rows  (64 M each)
    const int wn   = wid >> 1;     // 4 warp cols  (32 N each)
    const int g    = lane >> 2;    // group id 0..7
    const int t    = lane & 3;     // thread-in-group 0..3
    const int mBase = blockIdx.y * BM;
    const int nBase = blockIdx.x * BN;

    const uint32_t smu = (uint32_t)__cvta_generic_to_shared(sm);

    // Stage loader: 512 x 16B chunks, 2 per thread.
    auto load_stage = [&](int buf, int k0) {
#pragma unroll
        for (int tt = 0; tt < 2; tt++) {
            int id   = tid + tt * 256;        // 0..511
            int mat  = id >> 8;               // 0:A 1:B
            int ci   = id & 255;
            int row  = ci >> 1;
            int half = ci & 1;                // k sub-offset 0 / 8
            const __half* gp = (mat == 0) ? g_Xh : g_W;
            int grow = ((mat == 0) ? mBase : nBase) + row;
            const __half* src = gp + (size_t)grow * HDIM + k0 + half * 8;
            uint32_t dst = smu + (uint32_t)(buf * STAGE_BYTES + mat * MAT_BYTES +
                                            row * (KSTRIDE * 2) + half * 16);
            asm volatile("cp.async.cg.shared.global [%0], [%1], 16;\n"
                         :: "r"(dst), "l"(src) : "memory");
        }
        asm volatile("cp.async.commit_group;" ::: "memory");
    };

    float acc[4][4][4];
#pragma unroll
    for (int i = 0; i < 4; i++)
#pragma unroll
        for (int j = 0; j < 4; j++)
#pragma unroll
            for (int q = 0; q < 4; q++) acc[i][j][q] = 0.f;

    load_stage(0, 0);
    load_stage(1, BK);

    for (int c = 0; c < NUM_CHUNKS; c++) {
        if (c >= NUM_CHUNKS - 2)
            asm volatile("cp.async.wait_group 0;" ::: "memory");
        else
            asm volatile("cp.async.wait_group 1;" ::: "memory");
        __syncthreads();

        const char* stage = sm + (c & 1) * STAGE_BYTES;
        const __half* Am = (const __half*)(stage + 0 * MAT_BYTES);
        const __half* Bm = (const __half*)(stage + 1 * MAT_BYTES);

        uint32_t aa[4][4], bb[4][2];
#pragma unroll
        for (int mi = 0; mi < 4; mi++) {
            int r0 = (wm * 64 + mi * 16 + g) * KSTRIDE;
            int r1 = r0 + 8 * KSTRIDE;
            aa[mi][0] = *(const uint32_t*)(Am + r0 + t * 2);
            aa[mi][1] = *(const uint32_t*)(Am + r1 + t * 2);
            aa[mi][2] = *(const uint32_t*)(Am + r0 + t * 2 + 8);
            aa[mi][3] = *(const uint32_t*)(Am + r1 + t * 2 + 8);
        }
#pragma unroll
        for (int nj = 0; nj < 4; nj++) {
            int rn = (wn * 32 + nj * 8 + g) * KSTRIDE;
            bb[nj][0] = *(const uint32_t*)(Bm + rn + t * 2);
            bb[nj][1] = *(const uint32_t*)(Bm + rn + t * 2 + 8);
        }

#pragma unroll
        for (int mi = 0; mi < 4; mi++)
#pragma unroll
            for (int nj = 0; nj < 4; nj++)
                mma16816(acc[mi][nj], aa[mi], bb[nj]);

        __syncthreads();
        if (c + 2 < NUM_CHUNKS) load_stage(c & 1, (c + 2) * BK);
    }

    // Store accumulators + bias to g_C
#pragma unroll
    for (int mi = 0; mi < 4; mi++) {
        int m0 = mBase + wm * 64 + mi * 16 + g;
#pragma unroll
        for (int nj = 0; nj < 4; nj++) {
            int col = nBase + wn * 32 + nj * 8 + t * 2;
            float b0 = g_bias[col];
            float b1 = g_bias[col + 1];
            float2 v0 = make_float2(acc[mi][nj][0] + b0, acc[mi][nj][1] + b1);
            float2 v1 = make_float2(acc[mi][nj][2] + b0, acc[mi][nj][3] + b1);
            *(float2*)(g_C + (size_t)m0 * C_LD + col) = v0;
            *(float2*)(g_C + (size_t)(m0 + 8) * C_LD + col) = v1;
        }
    }
}

// ---------------------------------------------------------------------------
// Last column (2048 = roo row 1023) in exact fp32: one warp per token.
// ---------------------------------------------------------------------------
__global__ __launch_bounds__(256)
void lastcol_kernel(const float* __restrict__ X,
                    const float* __restrict__ W_roo,
                    const float* __restrict__ b_roo) {
    __shared__ float w[HDIM];
    const int tid = threadIdx.x;
    for (int j = tid; j < HDIM; j += 256)
        w[j] = W_roo[(size_t)(SPN - 1) * HDIM + j];
    __syncthreads();

    const int warp = tid >> 5, lane = tid & 31;
    const int n = blockIdx.x * 8 + warp;
    const float* x = X + (size_t)n * HDIM;
    float s = 0.f;
    for (int j = lane * 4; j < HDIM; j += 128) {
        float4 v = *(const float4*)(x + j);
        float4 wv = *(const float4*)(w + j);
        s += v.x * wv.x + v.y * wv.y + v.z * wv.z + v.w * wv.w;
    }
#pragma unroll
    for (int o = 16; o > 0; o >>= 1) s += __shfl_xor_sync(0xffffffffu, s, o);
    if (lane == 0)
        g_C[(size_t)n * C_LD + 2048] = s + b_roo[SPN - 1];
}

// ---------------------------------------------------------------------------
// Epilogue: per-token sigmoid + two softmaxes + gather + masked scatter.
// ---------------------------------------------------------------------------
__global__ __launch_bounds__(256)
void epilogue_kernel(const int* __restrict__ pY, const int* __restrict__ Yv,
                     float* __restrict__ out) {
    const int n = blockIdx.x;
    const float* Crow = g_C + (size_t)n * C_LD;
    __shared__ float sm[FPN + SPN];
    __shared__ float red[16];
    const int tid = threadIdx.x;
    const int lane = tid & 31, warp = tid >> 5;

    for (int j = tid; j < FPN + SPN; j += 256) sm[j] = Crow[1 + j];
    __syncthreads();

    float mh = -INFINITY, mr = -INFINITY;
    for (int j = tid; j < FPN; j += 256) mh = fmaxf(mh, sm[j]);
    for (int j = tid; j < SPN; j += 256) mr = fmaxf(mr, sm[FPN + j]);
#pragma unroll
    for (int o = 16; o > 0; o >>= 1) {
        mh = fmaxf(mh, __shfl_xor_sync(0xffffffffu, mh, o));
        mr = fmaxf(mr, __shfl_xor_sync(0xffffffffu, mr, o));
    }
    if (lane == 0) { red[warp] = mh; red[8 + warp] = mr; }
    __syncthreads();
    mh = red[0]; mr = red[8];
#pragma unroll
    for (int w = 1; w < 8; w++) {
        mh = fmaxf(mh, red[w]);
        mr = fmaxf(mr, red[8 + w]);
    }

    float sh = 0.f, sr = 0.f;
    for (int j = tid; j < FPN; j += 256) { float e = __expf(sm[j] - mh); sm[j] = e; sh += e; }
    for (int j = tid; j < SPN; j += 256) { float e = __expf(sm[FPN + j] - mr); sm[FPN + j] = e; sr += e; }
#pragma unroll
    for (int o = 16; o > 0; o >>= 1) {
        sh += __shfl_xor_sync(0xffffffffu, sh, o);
        sr += __shfl_xor_sync(0xffffffffu, sr, o);
    }
    __syncthreads();
    if (lane == 0) { red[warp] = sh; red[8 + warp] = sr; }
    __syncthreads();
    sh = 0.f; sr = 0.f;
#pragma unroll
    for (int w = 0; w < 8; w++) { sh += red[w]; sr += red[8 + w]; }

    const float inv_sh = 1.f / sh;
    const float inv_sr = 1.f / sr;
    const float end_logit = Crow[0];
    const float end_prob = 1.f / (1.f + __expf(-end_logit));
    const float non_end = 1.f - end_prob;

    const int ty = pY[n];

    float* orow = out + NTOK + (size_t)n * OUT_COLS;
    const float fe = (ty == 0) ? end_prob : 0.f;
    const float fh = (ty == 1) ? non_end * inv_sh : 0.f;
    const float fr = (ty == 2) ? non_end * inv_sr : 0.f;
    for (int j = tid; j < OUT_COLS; j += 256) {
        float v;
        if (j < 2)            v = fe;
        else if (j < 2 + FPN) v = sm[j - 2] * fh;
        else                  v = sm[j - 2] * fr;
        orow[j] = v;
    }

    if (tid == 0) {
        const int y = Yv[n];
        float prob;
        if (ty == 0) {
            prob = end_prob;
        } else if (ty == 1) {
            int idx = y - 2; idx = idx < 0 ? 0 : (idx > FPN - 1 ? FPN - 1 : idx);
            prob = sm[idx] * inv_sh * non_end;
        } else if (ty == 2) {
            int idx = y - 2 - FPN; idx = idx < 0 ? 0 : (idx > SPN - 1 ? SPN - 1 : idx);
            prob = sm[FPN + idx] * inv_sr * non_end;
        } else {
            prob = 1.f;
        }
        out[n] = logf(prob);
    }
}

// ---------------------------------------------------------------------------
// Launch
// ---------------------------------------------------------------------------
extern "C" void kernel_launch(void* const* d_in, const int* in_sizes, int n_in,
                              void* d_out, int out_size) {
    const float* X     = (const float*)d_in[0];
    const int*   pY    = (const int*)d_in[1];
    const int*   Yv    = (const int*)d_in[2];
    const float* W_end = (const float*)d_in[3];
    const float* b_end = (const float*)d_in[4];
    const float* W_hcw = (const float*)d_in[5];
    const float* b_hcw = (const float*)d_in[6];
    const float* W_roo = (const float*)d_in[7];
    const float* b_roo = (const float*)d_in[8];
    float* out = (float*)d_out;

    convert_x_kernel<<<2048, 256>>>(X);
    pack_w_kernel<<<2048, 256>>>(W_end, b_end, W_hcw, b_hcw, W_roo, b_roo);

    dim3 grid(NTILES, NTOK / BM);   // (16, 128) — cols 0..2047
    gemm_kernel<<<grid, 256>>>();

    lastcol_kernel<<<NTOK / 8, 256>>>(X, W_roo, b_roo);   // col 2048

    epilogue_kernel<<<NTOK, 256>>>(pY, Yv, out);
}

// round 11
// speedup vs baseline: 9.8256x; 2.2945x over previous
#include <cuda_runtime.h>
#include <cuda_fp16.h>
#include <stdint.h>
#include <math.h>

// ---------------------------------------------------------------------------
// Problem constants
// ---------------------------------------------------------------------------
#define NTOK 16384      // B*S
#define HDIM 2048
#define FPN  1024
#define SPN  1024
#define OUT_COLS 2050
#define NPAD  2304      // padded rows in packed W
#define LPAD  1032      // g_L row stride (floats)

// GEMM tiling (mma.sync m16n8k16, 8 warps, warp tile 64x32)
#define BM 128
#define BN 128
#define BK 16
#define NUM_CHUNKS (HDIM / BK)       // 128
#define KSTRIDE 24                   // padded fp16 elems per smem row (48B)
#define MAT_BYTES (128 * KSTRIDE * 2)    // 6144
#define STAGE_BYTES (2 * MAT_BYTES)      // A|B = 12288

// ---------------------------------------------------------------------------
// Device scratch
// ---------------------------------------------------------------------------
__device__ __align__(128) __half g_Xh[(size_t)NTOK * HDIM];
__device__ __align__(128) __half g_W[(size_t)NPAD * HDIM];
__device__ float g_bias[NPAD];
__device__ __align__(128) float g_L[(size_t)NTOK * LPAD];  // per-token own-block logits
__device__ float g_end[NTOK];                              // end logits
__device__ int g_cnt[2];        // raw class counts (ty==1, ty==2)
__device__ int g_cntp[2];       // padded counts
__device__ int g_idx[2][NTOK + BM];

// ---------------------------------------------------------------------------
// Zero counters
// ---------------------------------------------------------------------------
__global__ void zero_kernel() {
    if (threadIdx.x < 2) { g_cnt[threadIdx.x] = 0; g_cntp[threadIdx.x] = 0; }
}

// ---------------------------------------------------------------------------
// Classify tokens into hcw / roo lists
// ---------------------------------------------------------------------------
__global__ void classify_kernel(const int* __restrict__ pY) {
    int n = blockIdx.x * blockDim.x + threadIdx.x;
    if (n < NTOK) {
        int t = pY[n];
        if (t == 1) g_idx[0][atomicAdd(&g_cnt[0], 1)] = n;
        else if (t == 2) g_idx[1][atomicAdd(&g_cnt[1], 1)] = n;
    }
}

// ---------------------------------------------------------------------------
// Pad lists to multiple of BM (duplicate first index; writes idempotent)
// ---------------------------------------------------------------------------
__global__ void pad_kernel() {
    for (int c = 0; c < 2; c++) {
        int cnt = g_cnt[c];
        int padded = (cnt + BM - 1) & ~(BM - 1);
        int fill = (cnt > 0) ? g_idx[c][0] : 0;
        for (int i = cnt + threadIdx.x; i < padded; i += blockDim.x)
            g_idx[c][i] = fill;
        if (threadIdx.x == 0) g_cntp[c] = padded;
    }
}

// ---------------------------------------------------------------------------
// Convert X -> fp16
// ---------------------------------------------------------------------------
__global__ void convert_x_kernel(const float* __restrict__ X) {
    const size_t total = (size_t)NTOK * HDIM / 4;
    for (size_t i = blockIdx.x * (size_t)blockDim.x + threadIdx.x; i < total;
         i += (size_t)gridDim.x * blockDim.x) {
        float4 v = ((const float4*)X)[i];
        __half h[4];
        h[0] = __float2half(v.x);
        h[1] = __float2half(v.y);
        h[2] = __float2half(v.z);
        h[3] = __float2half(v.w);
        ((uint2*)g_Xh)[i] = *(uint2*)h;
    }
}

// ---------------------------------------------------------------------------
// Pack W_end/W_hcw/W_roo -> fp16 [NPAD, HDIM] + bias
// Row 0: end; rows 1..1024: hcw; rows 1025..2048: roo; rest zero.
// ---------------------------------------------------------------------------
__global__ void pack_w_kernel(const float* __restrict__ W_end,
                              const float* __restrict__ b_end,
                              const float* __restrict__ W_hcw,
                              const float* __restrict__ b_hcw,
                              const float* __restrict__ W_roo,
                              const float* __restrict__ b_roo) {
    const size_t total = (size_t)NPAD * HDIM / 4;
    for (size_t i = blockIdx.x * (size_t)blockDim.x + threadIdx.x; i < total;
         i += (size_t)gridDim.x * blockDim.x) {
        size_t e = i * 4;
        int row = (int)(e >> 11);
        int k   = (int)(e & (HDIM - 1));
        float4 v = make_float4(0.f, 0.f, 0.f, 0.f);
        if (row == 0)              v = *(const float4*)(W_end + k);
        else if (row <= FPN)       v = *(const float4*)(W_hcw + (size_t)(row - 1) * HDIM + k);
        else if (row <= FPN + SPN) v = *(const float4*)(W_roo + (size_t)(row - 1 - FPN) * HDIM + k);
        __half h[4];
        h[0] = __float2half(v.x);
        h[1] = __float2half(v.y);
        h[2] = __float2half(v.z);
        h[3] = __float2half(v.w);
        ((uint2*)g_W)[i] = *(uint2*)h;
    }
    int idx = blockIdx.x * blockDim.x + threadIdx.x;
    if (idx < NPAD) {
        float b = 0.f;
        if (idx == 0)              b = b_end[0];
        else if (idx <= FPN)       b = b_hcw[idx - 1];
        else if (idx <= FPN + SPN) b = b_roo[idx - 1 - FPN];
        g_bias[idx] = b;
    }
}

// ---------------------------------------------------------------------------
// End-head GEMV: g_end[n] = g_Xh[n,:] . W_end + b_end   (one warp per token)
// ---------------------------------------------------------------------------
__global__ __launch_bounds__(256)
void end_gemv_kernel(const float* __restrict__ W_end,
                     const float* __restrict__ b_end) {
    __shared__ float w[HDIM];
    const int tid = threadIdx.x;
    for (int j = tid; j < HDIM; j += 256) w[j] = W_end[j];
    __syncthreads();

    const int warp = tid >> 5, lane = tid & 31;
    const int n = blockIdx.x * 8 + warp;
    const __half* x = g_Xh + (size_t)n * HDIM;
    float s = 0.f;
    for (int j = lane * 4; j < HDIM; j += 128) {
        uint2 p = *(const uint2*)(x + j);
        __half2 h0 = *(__half2*)&p.x;
        __half2 h1 = *(__half2*)&p.y;
        float2 f0 = __half22float2(h0);
        float2 f1 = __half22float2(h1);
        s += f0.x * w[j] + f0.y * w[j + 1] + f1.x * w[j + 2] + f1.y * w[j + 3];
    }
#pragma unroll
    for (int o = 16; o > 0; o >>= 1) s += __shfl_xor_sync(0xffffffffu, s, o);
    if (lane == 0) g_end[n] = s + b_end[0];
}

// ---------------------------------------------------------------------------
// mma.sync helper (fp16 in, fp32 accumulate)
// ---------------------------------------------------------------------------
__device__ __forceinline__ void mma16816(float* c, const uint32_t* a,
                                         const uint32_t* b) {
    asm volatile(
        "mma.sync.aligned.m16n8k16.row.col.f32.f16.f16.f32 "
        "{%0,%1,%2,%3}, {%4,%5,%6,%7}, {%8,%9}, {%0,%1,%2,%3};"
        : "+f"(c[0]), "+f"(c[1]), "+f"(c[2]), "+f"(c[3])
        : "r"(a[0]), "r"(a[1]), "r"(a[2]), "r"(a[3]), "r"(b[0]), "r"(b[1]));
}

// ---------------------------------------------------------------------------
// Gather-GEMM: for class cls (0=hcw, 1=roo), tokens from g_idx[cls],
// g_L[token, 0..1023] = Xh[token,:] @ W[1+cls*1024 + col,:] + bias
// grid (8, 128, 2); CTAs beyond padded count exit.
// ---------------------------------------------------------------------------
__global__ void __launch_bounds__(256, 1) gemm_kernel() {
    const int cls = blockIdx.z;
    const int mTile = blockIdx.y * BM;
    if (mTile >= g_cntp[cls]) return;

    __shared__ __align__(16) char sm[2 * STAGE_BYTES];
    __shared__ int sidx[BM];

    const int tid  = threadIdx.x;
    const int wid  = tid >> 5;
    const int lane = tid & 31;
    const int wm   = wid & 1;
    const int wn   = wid >> 1;
    const int g    = lane >> 2;
    const int t    = lane & 3;

    if (tid < BM) sidx[tid] = g_idx[cls][mTile + tid];
    __syncthreads();

    const uint32_t smu = (uint32_t)__cvta_generic_to_shared(sm);

    // Per-thread fixed source rows: A row = sidx[tid>>1], B row = wbase + tid>>1
    const int wbase = 1 + cls * 1024 + blockIdx.x * BN;
    const __half* asrc = g_Xh + (size_t)sidx[tid >> 1] * HDIM + (tid & 1) * 8;
    const __half* bsrc = g_W + (size_t)(wbase + (tid >> 1)) * HDIM + (tid & 1) * 8;
    const uint32_t adst = smu + (uint32_t)((tid >> 1) * (KSTRIDE * 2) + (tid & 1) * 16);
    const uint32_t bdst = adst + MAT_BYTES;

    auto load_stage = [&](int buf, int k0) {
        asm volatile("cp.async.cg.shared.global [%0], [%1], 16;\n"
                     :: "r"(adst + buf * STAGE_BYTES), "l"(asrc + k0) : "memory");
        asm volatile("cp.async.cg.shared.global [%0], [%1], 16;\n"
                     :: "r"(bdst + buf * STAGE_BYTES), "l"(bsrc + k0) : "memory");
        asm volatile("cp.async.commit_group;" ::: "memory");
    };

    float acc[4][4][4];
#pragma unroll
    for (int i = 0; i < 4; i++)
#pragma unroll
        for (int j = 0; j < 4; j++)
#pragma unroll
            for (int q = 0; q < 4; q++) acc[i][j][q] = 0.f;

    load_stage(0, 0);
    load_stage(1, BK);

    for (int c = 0; c < NUM_CHUNKS; c++) {
        if (c >= NUM_CHUNKS - 2)
            asm volatile("cp.async.wait_group 0;" ::: "memory");
        else
            asm volatile("cp.async.wait_group 1;" ::: "memory");
        __syncthreads();

        const char* stage = sm + (c & 1) * STAGE_BYTES;
        const __half* Am = (const __half*)(stage);
        const __half* Bm = (const __half*)(stage + MAT_BYTES);

        uint32_t aa[4][4], bb[4][2];
#pragma unroll
        for (int mi = 0; mi < 4; mi++) {
            int r0 = (wm * 64 + mi * 16 + g) * KSTRIDE;
            int r1 = r0 + 8 * KSTRIDE;
            aa[mi][0] = *(const uint32_t*)(Am + r0 + t * 2);
            aa[mi][1] = *(const uint32_t*)(Am + r1 + t * 2);
            aa[mi][2] = *(const uint32_t*)(Am + r0 + t * 2 + 8);
            aa[mi][3] = *(const uint32_t*)(Am + r1 + t * 2 + 8);
        }
#pragma unroll
        for (int nj = 0; nj < 4; nj++) {
            int rn = (wn * 32 + nj * 8 + g) * KSTRIDE;
            bb[nj][0] = *(const uint32_t*)(Bm + rn + t * 2);
            bb[nj][1] = *(const uint32_t*)(Bm + rn + t * 2 + 8);
        }

#pragma unroll
        for (int mi = 0; mi < 4; mi++)
#pragma unroll
            for (int nj = 0; nj < 4; nj++)
                mma16816(acc[mi][nj], aa[mi], bb[nj]);

        __syncthreads();
        if (c + 2 < NUM_CHUNKS) load_stage(c & 1, (c + 2) * BK);
    }

    // Store to g_L rows (scatter by token), bias folded
#pragma unroll
    for (int mi = 0; mi < 4; mi++) {
        int lm = wm * 64 + mi * 16 + g;
        int tok0 = sidx[lm];
        int tok1 = sidx[lm + 8];
#pragma unroll
        for (int nj = 0; nj < 4; nj++) {
            int col = blockIdx.x * BN + wn * 32 + nj * 8 + t * 2;
            float b0 = g_bias[wbase - blockIdx.x * BN + col];       // = 1+cls*1024+col
            float b1 = g_bias[wbase - blockIdx.x * BN + col + 1];
            float2 v0 = make_float2(acc[mi][nj][0] + b0, acc[mi][nj][1] + b1);
            float2 v1 = make_float2(acc[mi][nj][2] + b0, acc[mi][nj][3] + b1);
            *(float2*)(g_L + (size_t)tok0 * LPAD + col) = v0;
            *(float2*)(g_L + (size_t)tok1 * LPAD + col) = v1;
        }
    }
}

// ---------------------------------------------------------------------------
// Epilogue: one CTA per token. Single softmax over own block (if any).
// out[0..NTOK): log_prob; out[NTOK..): prob_all [NTOK, 2050].
// ---------------------------------------------------------------------------
__global__ __launch_bounds__(256)
void epilogue_kernel(const int* __restrict__ pY, const int* __restrict__ Yv,
                     float* __restrict__ out) {
    const int n = blockIdx.x;
    const int tid = threadIdx.x;
    const int lane = tid & 31, warp = tid >> 5;
    const int ty = pY[n];

    const float end_logit = g_end[n];
    const float end_prob = 1.f / (1.f + __expf(-end_logit));
    const float non_end = 1.f - end_prob;

    float* orow = out + NTOK + (size_t)n * OUT_COLS;

    if (ty == 0 || ty > 2) {
        // end-only token: [end_prob, end_prob, 0, ..., 0]
        const float fe = (ty == 0) ? end_prob : 0.f;
        for (int j = tid * 2; j < OUT_COLS; j += 512) {
            float2 v = make_float2(j < 2 ? fe : 0.f, (j + 1) < 2 ? fe : 0.f);
            *(float2*)(orow + j) = v;
        }
        if (tid == 0)
            out[n] = logf(ty == 0 ? end_prob : 1.f);
        return;
    }

    __shared__ float sm[1024];
    __shared__ float red[8];
    const float* Lrow = g_L + (size_t)n * LPAD;

    // load
    {
        float4 v = *(const float4*)(Lrow + tid * 4);
        *(float4*)(sm + tid * 4) = v;
    }
    __syncthreads();

    // max
    float mx = -INFINITY;
#pragma unroll
    for (int q = 0; q < 4; q++) mx = fmaxf(mx, sm[tid + q * 256]);
#pragma unroll
    for (int o = 16; o > 0; o >>= 1)
        mx = fmaxf(mx, __shfl_xor_sync(0xffffffffu, mx, o));
    if (lane == 0) red[warp] = mx;
    __syncthreads();
    mx = red[0];
#pragma unroll
    for (int w = 1; w < 8; w++) mx = fmaxf(mx, red[w]);

    // exp + sum
    float s = 0.f;
#pragma unroll
    for (int q = 0; q < 4; q++) {
        float e = __expf(sm[tid + q * 256] - mx);
        sm[tid + q * 256] = e;
        s += e;
    }
#pragma unroll
    for (int o = 16; o > 0; o >>= 1) s += __shfl_xor_sync(0xffffffffu, s, o);
    __syncthreads();
    if (lane == 0) red[warp] = s;
    __syncthreads();
    s = 0.f;
#pragma unroll
    for (int w = 0; w < 8; w++) s += red[w];

    const float f = non_end / s;

    // write: block region [blo, bhi), zeros elsewhere
    const int blo = (ty == 1) ? 2 : 1026;
    const int bhi = blo + 1024;
    for (int j = tid * 2; j < OUT_COLS; j += 512) {
        float2 v;
        v.x = (j >= blo && j < bhi) ? sm[j - blo] * f : 0.f;
        v.y = (j + 1 >= blo && j + 1 < bhi) ? sm[j + 1 - blo] * f : 0.f;
        *(float2*)(orow + j) = v;
    }

    if (tid == 0) {
        const int y = Yv[n];
        int idx = (ty == 1) ? (y - 2) : (y - 2 - FPN);
        idx = idx < 0 ? 0 : (idx > 1023 ? 1023 : idx);
        out[n] = logf(sm[idx] * f);
    }
}

// ---------------------------------------------------------------------------
// Launch
// ---------------------------------------------------------------------------
extern "C" void kernel_launch(void* const* d_in, const int* in_sizes, int n_in,
                              void* d_out, int out_size) {
    const float* X     = (const float*)d_in[0];
    const int*   pY    = (const int*)d_in[1];
    const int*   Yv    = (const int*)d_in[2];
    const float* W_end = (const float*)d_in[3];
    const float* b_end = (const float*)d_in[4];
    const float* W_hcw = (const float*)d_in[5];
    const float* b_hcw = (const float*)d_in[6];
    const float* W_roo = (const float*)d_in[7];
    const float* b_roo = (const float*)d_in[8];
    float* out = (float*)d_out;

    zero_kernel<<<1, 32>>>();
    classify_kernel<<<NTOK / 256, 256>>>(pY);
    pad_kernel<<<1, 256>>>();

    convert_x_kernel<<<2048, 256>>>(X);
    pack_w_kernel<<<2048, 256>>>(W_end, b_end, W_hcw, b_hcw, W_roo, b_roo);

    end_gemv_kernel<<<NTOK / 8, 256>>>(W_end, b_end);

    dim3 grid(8, NTOK / BM, 2);   // (8, 128, 2); inactive tiles exit early
    gemm_kernel<<<grid, 256>>>();

    epilogue_kernel<<<NTOK, 256>>>(pY, Yv, out);
}